// round 1
// baseline (speedup 1.0000x reference)
#include <cuda_runtime.h>
#include <cstdint>

// ---------------------------------------------------------------------------
// CTRGC fused kernel.
// out[n,o,t,w] = relu( sum_k sum_v (sum_c Weff[k][o,c] * x[n,c,t,v]) * M_k[v,w] + Ceff[o] )
// with all BN affines folded into Weff / Ceff, attention branch dead.
// Shapes: N=128, Cin=Cout=64, T=256, V=18, K=3.
// ---------------------------------------------------------------------------

#define KNUM 3
#define CIN 64
#define COUT 64
#define TLEN 256
#define VD 18
#define VP 20          // padded row (16B-aligned rows)
#define TT 8           // t's per CTA
#define THREADS 512
#define NBLOCKS 1036   // 7 * 148
#define NTILES (128 * (TLEN / TT))

// prepped parameters (device globals: no allocation allowed)
__device__ float d_Wpack[CIN * COUT * 4];   // [c][o][k0,k1,k2,pad]
__device__ float d_Cf[COUT];
__device__ float d_M[KNUM * VD * VP];       // [k][v][w padded]

__global__ void prep_kernel(const float* __restrict__ A, const float* __restrict__ PA,
                            const float* __restrict__ Wta, const float* __restrict__ bta,
                            const float* __restrict__ g_ta, const float* __restrict__ b_ta,
                            const float* __restrict__ m_ta, const float* __restrict__ v_ta,
                            const float* __restrict__ g_bn, const float* __restrict__ b_bn,
                            const float* __restrict__ m_bn, const float* __restrict__ v_bn)
{
    int tid = threadIdx.x;
    for (int idx = tid; idx < CIN * COUT; idx += blockDim.x) {
        int c = idx >> 6, o = idx & 63;
        float s2 = g_bn[o] * rsqrtf(v_bn[o] + 1e-5f);
        float w0, w1, w2;
        {
            float s1 = g_ta[0 * 64 + o] * rsqrtf(v_ta[0 * 64 + o] + 1e-5f);
            w0 = s2 * s1 * Wta[(0 * 64 + o) * 64 + c];
        }
        {
            float s1 = g_ta[1 * 64 + o] * rsqrtf(v_ta[1 * 64 + o] + 1e-5f);
            w1 = s2 * s1 * Wta[(1 * 64 + o) * 64 + c];
        }
        {
            float s1 = g_ta[2 * 64 + o] * rsqrtf(v_ta[2 * 64 + o] + 1e-5f);
            w2 = s2 * s1 * Wta[(2 * 64 + o) * 64 + c];
        }
        float4 wv = make_float4(w0, w1, w2, 0.0f);
        *reinterpret_cast<float4*>(d_Wpack + idx * 4) = wv;
    }
    if (tid < COUT) {
        int o = tid;
        float s2 = g_bn[o] * rsqrtf(v_bn[o] + 1e-5f);
        float acc = 0.0f;
        for (int k = 0; k < KNUM; k++) {
            float s1 = g_ta[k * 64 + o] * rsqrtf(v_ta[k * 64 + o] + 1e-5f);
            acc += s1 * bta[k * 64 + o] + b_ta[k * 64 + o] - m_ta[k * 64 + o] * s1;
        }
        d_Cf[o] = s2 * acc + b_bn[o] - m_bn[o] * s2;
    }
    for (int idx = tid; idx < KNUM * VD * VP; idx += blockDim.x) {
        int k = idx / (VD * VP);
        int r = idx - k * (VD * VP);
        int v = r / VP;
        int w = r - v * VP;
        d_M[idx] = (w < VD) ? (A[(k * VD + v) * VD + w] + PA[(k * VD + v) * VD + w]) : 0.0f;
    }
}

// ---- packed f32x2 helpers (Blackwell-only FFMA2, PTX path) ----
__device__ __forceinline__ unsigned long long pk2(float a, float b) {
    unsigned long long r;
    asm("mov.b64 %0, {%1,%2};" : "=l"(r) : "f"(a), "f"(b));
    return r;
}
__device__ __forceinline__ void upk2(unsigned long long p, float& a, float& b) {
    asm("mov.b64 {%0,%1}, %2;" : "=f"(a), "=f"(b) : "l"(p));
}
__device__ __forceinline__ unsigned long long fma2(unsigned long long a,
                                                   unsigned long long b,
                                                   unsigned long long c) {
    unsigned long long d;
    asm("fma.rn.f32x2 %0, %1, %2, %3;" : "=l"(d) : "l"(a), "l"(b), "l"(c));
    return d;
}

extern __shared__ float smem[];

__global__ __launch_bounds__(THREADS, 1)
void ctrgc_main(const float* __restrict__ x, float* __restrict__ out)
{
    // smem layout (floats): sW 16384 | sM 1080 | sC 64 | sx TT*64*VP = 10240
    float* sW = smem;
    float* sM = sW + CIN * COUT * 4;
    float* sC = sM + KNUM * VD * VP;
    float* sx = sC + COUT;

    int tid = threadIdx.x;
    for (int i = tid; i < CIN * COUT * 4; i += THREADS) sW[i] = d_Wpack[i];
    for (int i = tid; i < KNUM * VD * VP; i += THREADS) sM[i] = d_M[i];
    if (tid < COUT) sC[tid] = d_Cf[tid];

    const int g = tid >> 6;   // 0..7  : t within tile
    const int o = tid & 63;   // 0..63 : output channel

    for (int tile = blockIdx.x; tile < NTILES; tile += gridDim.x) {
        int n  = tile >> 5;            // TLEN/TT = 32
        int t0 = (tile & 31) * TT;

        __syncthreads();  // protects sx reuse (and first-iter param fill)

        // load x tile: x[n][c][t0..t0+TT-1][0..17] -> sx[t][c][VP]
        const float* xn = x + (size_t)n * (CIN * TLEN * VD) + (size_t)t0 * VD;
        for (int i = tid; i < CIN * TT * VD; i += THREADS) {
            int c = i / (TT * VD);
            int j = i - c * (TT * VD);
            int t = j / VD;
            int v = j - t * VD;
            sx[(t * CIN + c) * VP + v] = xn[c * (TLEN * VD) + j];
        }
        __syncthreads();

        // ---- stage A: Y[k][v] = sum_c Weff[k][o,c] * x[c,v]  (v packed in f32x2)
        unsigned long long Y[KNUM][9];
#pragma unroll
        for (int k = 0; k < KNUM; k++)
#pragma unroll
            for (int p = 0; p < 9; p++) Y[k][p] = 0ull;

        const float* xr = sx + g * (CIN * VP);
#pragma unroll 8
        for (int c = 0; c < CIN; c++) {
            float4 wv = *reinterpret_cast<const float4*>(sW + (c * COUT + o) * 4);
            const float* row = xr + c * VP;
            ulonglong2 xA = *reinterpret_cast<const ulonglong2*>(row);
            ulonglong2 xB = *reinterpret_cast<const ulonglong2*>(row + 4);
            ulonglong2 xC = *reinterpret_cast<const ulonglong2*>(row + 8);
            ulonglong2 xD = *reinterpret_cast<const ulonglong2*>(row + 12);
            unsigned long long xE = *reinterpret_cast<const unsigned long long*>(row + 16);
            unsigned long long w0 = pk2(wv.x, wv.x);
            unsigned long long w1 = pk2(wv.y, wv.y);
            unsigned long long w2 = pk2(wv.z, wv.z);
            unsigned long long xs[9] = {xA.x, xA.y, xB.x, xB.y, xC.x, xC.y, xD.x, xD.y, xE};
#pragma unroll
            for (int p = 0; p < 9; p++) {
                Y[0][p] = fma2(w0, xs[p], Y[0][p]);
                Y[1][p] = fma2(w1, xs[p], Y[1][p]);
                Y[2][p] = fma2(w2, xs[p], Y[2][p]);
            }
        }

        // ---- stage B: O[w] = Ceff[o] + sum_k sum_v Y[k][v] * M_k[v][w]
        float cf = sC[o];
        unsigned long long cp = pk2(cf, cf);
        unsigned long long O[9];
#pragma unroll
        for (int p = 0; p < 9; p++) O[p] = cp;

#pragma unroll
        for (int k = 0; k < KNUM; k++) {
#pragma unroll
            for (int pv = 0; pv < 9; pv++) {
                float ya, yb;
                upk2(Y[k][pv], ya, yb);
                unsigned long long Ya = pk2(ya, ya);
                unsigned long long Yb = pk2(yb, yb);
                const float* m0 = sM + (k * VD + 2 * pv) * VP;
                {
                    ulonglong2 a0 = *reinterpret_cast<const ulonglong2*>(m0);
                    ulonglong2 a1 = *reinterpret_cast<const ulonglong2*>(m0 + 4);
                    ulonglong2 a2 = *reinterpret_cast<const ulonglong2*>(m0 + 8);
                    ulonglong2 a3 = *reinterpret_cast<const ulonglong2*>(m0 + 12);
                    unsigned long long a4 = *reinterpret_cast<const unsigned long long*>(m0 + 16);
                    O[0] = fma2(Ya, a0.x, O[0]); O[1] = fma2(Ya, a0.y, O[1]);
                    O[2] = fma2(Ya, a1.x, O[2]); O[3] = fma2(Ya, a1.y, O[3]);
                    O[4] = fma2(Ya, a2.x, O[4]); O[5] = fma2(Ya, a2.y, O[5]);
                    O[6] = fma2(Ya, a3.x, O[6]); O[7] = fma2(Ya, a3.y, O[7]);
                    O[8] = fma2(Ya, a4,   O[8]);
                }
                const float* m1 = m0 + VP;
                {
                    ulonglong2 b0 = *reinterpret_cast<const ulonglong2*>(m1);
                    ulonglong2 b1 = *reinterpret_cast<const ulonglong2*>(m1 + 4);
                    ulonglong2 b2 = *reinterpret_cast<const ulonglong2*>(m1 + 8);
                    ulonglong2 b3 = *reinterpret_cast<const ulonglong2*>(m1 + 12);
                    unsigned long long b4 = *reinterpret_cast<const unsigned long long*>(m1 + 16);
                    O[0] = fma2(Yb, b0.x, O[0]); O[1] = fma2(Yb, b0.y, O[1]);
                    O[2] = fma2(Yb, b1.x, O[2]); O[3] = fma2(Yb, b1.y, O[3]);
                    O[4] = fma2(Yb, b2.x, O[4]); O[5] = fma2(Yb, b2.y, O[5]);
                    O[6] = fma2(Yb, b3.x, O[6]); O[7] = fma2(Yb, b3.y, O[7]);
                    O[8] = fma2(Yb, b4,   O[8]);
                }
            }
        }

        // ---- epilogue: relu + store (8B-aligned float2 stores)
        float* op = out + ((size_t)(n * COUT + o) * TLEN + (t0 + g)) * VD;
#pragma unroll
        for (int p = 0; p < 9; p++) {
            float a, b;
            upk2(O[p], a, b);
            float2 st = make_float2(fmaxf(a, 0.0f), fmaxf(b, 0.0f));
            *reinterpret_cast<float2*>(op + 2 * p) = st;
        }
    }
}

static const int SMEM_BYTES = (CIN * COUT * 4 + KNUM * VD * VP + COUT + TT * CIN * VP) * 4;

extern "C" void kernel_launch(void* const* d_in, const int* in_sizes, int n_in,
                              void* d_out, int out_size)
{
    (void)in_sizes; (void)n_in; (void)out_size;
    const float* x    = (const float*)d_in[0];
    const float* A    = (const float*)d_in[1];
    const float* PA   = (const float*)d_in[2];
    const float* Wta  = (const float*)d_in[3];
    const float* bta  = (const float*)d_in[4];
    const float* g_ta = (const float*)d_in[5];
    const float* b_ta = (const float*)d_in[6];
    const float* m_ta = (const float*)d_in[7];
    const float* v_ta = (const float*)d_in[8];
    // d_in[9..12] = Wsa, bsa, Wsb, bsb : dead branch, unused
    const float* g_bn = (const float*)d_in[13];
    const float* b_bn = (const float*)d_in[14];
    const float* m_bn = (const float*)d_in[15];
    const float* v_bn = (const float*)d_in[16];
    float* out = (float*)d_out;

    cudaFuncSetAttribute(ctrgc_main, cudaFuncAttributeMaxDynamicSharedMemorySize, SMEM_BYTES);

    prep_kernel<<<1, 256>>>(A, PA, Wta, bta, g_ta, b_ta, m_ta, v_ta,
                            g_bn, b_bn, m_bn, v_bn);
    ctrgc_main<<<NBLOCKS, THREADS, SMEM_BYTES>>>(x, out);
}